// round 4
// baseline (speedup 1.0000x reference)
#include <cuda_runtime.h>
#include <math.h>

#define H 1024
#define W 1024
#define HW (H*W)
#define TX 64
#define TY 32
#define SGX 72
#define SGY 40
#define SBX 68
#define SBY 36
#define SMX 66
#define SMY 34
#define NT 512

typedef unsigned long long u64;

__device__ int g_count = 0;
__device__ int g_ticket = 0;

__device__ __forceinline__ u64 pk(float lo, float hi) {
    u64 r; asm("mov.b64 %0,{%1,%2};" : "=l"(r) : "f"(lo), "f"(hi)); return r;
}
__device__ __forceinline__ void upk(u64 v, float& lo, float& hi) {
    asm("mov.b64 {%0,%1},%2;" : "=f"(lo), "=f"(hi) : "l"(v));
}
__device__ __forceinline__ u64 fadd2(u64 a, u64 b) {
    u64 r; asm("add.rn.f32x2 %0,%1,%2;" : "=l"(r) : "l"(a), "l"(b)); return r;
}
__device__ __forceinline__ u64 fmul2(u64 a, u64 b) {
    u64 r; asm("mul.rn.f32x2 %0,%1,%2;" : "=l"(r) : "l"(a), "l"(b)); return r;
}
__device__ __forceinline__ u64 ffma2(u64 a, u64 b, u64 c) {
    u64 r; asm("fma.rn.f32x2 %0,%1,%2,%3;" : "=l"(r) : "l"(a), "l"(b), "l"(c)); return r;
}
__device__ __forceinline__ u64 fneg2(u64 a) { return a ^ 0x8000000080000000ULL; }
__device__ __forceinline__ u64 fsub2(u64 a, u64 b) { return fadd2(a, fneg2(b)); }

__device__ __forceinline__ int reflecti(int c, int n) {
    if (c < 0) c = -c;
    if (c >= n) c = 2*n - 2 - c;
    return c;
}
__device__ __forceinline__ int clampi(int c, int n) {
    return min(max(c, 0), n - 1);
}

#define GW0 0.05448868454964294f
#define GW1 0.24420134723186663f
#define GW2 0.4026199364369709f
#define T_LO 0.41421356237309503f
#define T_HI 2.414213562373095f
#define TH2  0.009999f

__device__ __forceinline__ int axis_off(float gx, float gy) {
    float ax = fabsf(gx), ay = fabsf(gy);
    if (ay <= T_LO * ax) return 1;
    if (ay >= T_HI * ax) return SMX;
    return ((__float_as_int(gx) ^ __float_as_int(gy)) >= 0) ? (SMX - 1) : (SMX + 1);
}

__device__ __forceinline__ u64 tap5(u64 t0, u64 t1, u64 t2, u64 t3, u64 t4,
                                    u64 K0, u64 K1, u64 K2) {
    u64 acc = fmul2(fadd2(t0, t4), K0);
    acc = ffma2(fadd2(t1, t3), K1, acc);
    return ffma2(t2, K2, acc);
}

__global__ __launch_bounds__(NT)
void edge_loss_kernel(const float* __restrict__ op, const float* __restrict__ gt,
                      float* __restrict__ out, float inv_n)
{
    __shared__ u64   sA[SGY * SGX];
    __shared__ u64   sB[SGY * SBX];
    __shared__ short snoff[TY * TX];
    __shared__ int   wsum[NT / 32];

    const int tid = threadIdx.x;
    const int x0 = blockIdx.x * TX;
    const int y0 = blockIdx.y * TY;
    const size_t ib = (size_t)blockIdx.z * 3 * HW;
    const float* __restrict__ opi = op + ib;
    const float* __restrict__ gti = gt + ib;
    const bool xfast = (x0 != 0) && (x0 != W - TX);
    const bool yfast = (y0 != 0) && (y0 != H - TY);

    const u64 K0 = pk(GW0, GW0), K1 = pk(GW1, GW1), K2 = pk(GW2, GW2);
    const u64 TWO = pk(2.0f, 2.0f);

    // ---- Stage 1: grayscale pairs (reflect halo 4) -> sA[SGY][SGX] ----
    if (xfast) {
        #pragma unroll 1
        for (int g = tid; g < SGY * 18; g += NT) {
            int i = g / 18, q = g - i * 18;
            int yy = reflecti(y0 - 4 + i, H);
            const float* po = opi + yy * W + (x0 - 4) + q * 4;
            const float* pg = gti + yy * W + (x0 - 4) + q * 4;
            float4 ro = *(const float4*)(po);
            float4 go = *(const float4*)(po + HW);
            float4 bo = *(const float4*)(po + 2 * HW);
            float4 rg = *(const float4*)(pg);
            float4 gg = *(const float4*)(pg + HW);
            float4 bg = *(const float4*)(pg + 2 * HW);
            float o0 = fmaf(0.299f, ro.x, fmaf(0.587f, go.x, 0.114f * bo.x));
            float o1 = fmaf(0.299f, ro.y, fmaf(0.587f, go.y, 0.114f * bo.y));
            float o2 = fmaf(0.299f, ro.z, fmaf(0.587f, go.z, 0.114f * bo.z));
            float o3 = fmaf(0.299f, ro.w, fmaf(0.587f, go.w, 0.114f * bo.w));
            float t0 = fmaf(0.299f, rg.x, fmaf(0.587f, gg.x, 0.114f * bg.x));
            float t1 = fmaf(0.299f, rg.y, fmaf(0.587f, gg.y, 0.114f * bg.y));
            float t2 = fmaf(0.299f, rg.z, fmaf(0.587f, gg.z, 0.114f * bg.z));
            float t3 = fmaf(0.299f, rg.w, fmaf(0.587f, gg.w, 0.114f * bg.w));
            u64* dst = &sA[i * SGX + q * 4];
            *(ulonglong2*)(dst)     = make_ulonglong2(pk(o0, t0), pk(o1, t1));
            *(ulonglong2*)(dst + 2) = make_ulonglong2(pk(o2, t2), pk(o3, t3));
        }
    } else {
        #pragma unroll 1
        for (int e = tid; e < SGY * SGX; e += NT) {
            int i = e / SGX, j = e - i * SGX;
            int yy = reflecti(y0 - 4 + i, H);
            int xx = reflecti(x0 - 4 + j, W);
            int o = yy * W + xx;
            float a = fmaf(0.299f, opi[o], fmaf(0.587f, opi[o + HW], 0.114f * opi[o + 2*HW]));
            float b = fmaf(0.299f, gti[o], fmaf(0.587f, gti[o + HW], 0.114f * gti[o + 2*HW]));
            sA[e] = pk(a, b);
        }
    }
    __syncthreads();

    // ---- Stage 2: hblur 4-wide -> sB[SGY][SBX] ----
    if (xfast) {
        #pragma unroll 1
        for (int s = tid; s < SGY * 17; s += NT) {
            int i = s / 17;
            int j4 = (s - i * 17) << 2;
            const ulonglong2* rv = (const ulonglong2*)&sA[i * SGX + j4];
            ulonglong2 p0 = rv[0], p1 = rv[1], p2 = rv[2], p3 = rv[3];
            u64 o0 = tap5(p0.x, p0.y, p1.x, p1.y, p2.x, K0, K1, K2);
            u64 o1 = tap5(p0.y, p1.x, p1.y, p2.x, p2.y, K0, K1, K2);
            u64 o2 = tap5(p1.x, p1.y, p2.x, p2.y, p3.x, K0, K1, K2);
            u64 o3 = tap5(p1.y, p2.x, p2.y, p3.x, p3.y, K0, K1, K2);
            ulonglong2* w = (ulonglong2*)&sB[i * SBX + j4];
            w[0] = make_ulonglong2(o0, o1);
            w[1] = make_ulonglong2(o2, o3);
        }
    } else {
        #pragma unroll 1
        for (int e = tid; e < SGY * SBX; e += NT) {
            int i = e / SBX, j = e - i * SBX;
            int jj = clampi(x0 - 2 + j, W) - (x0 - 4);
            const u64* row = &sA[i * SGX + jj];
            sB[e] = tap5(row[-2], row[-1], row[0], row[1], row[2], K0, K1, K2);
        }
    }
    __syncthreads();

    // ---- Stage 3: vblur 4-tall x 2-wide -> sA[SBY][SBX] ----
    if (yfast) {
        #pragma unroll 1
        for (int s = tid; s < 9 * 34; s += NT) {
            int rg = s / 34;
            int j2 = (s - rg * 34) << 1;
            int r0 = rg << 2;
            ulonglong2 t0 = *(const ulonglong2*)&sB[(r0+0) * SBX + j2];
            ulonglong2 t1 = *(const ulonglong2*)&sB[(r0+1) * SBX + j2];
            ulonglong2 t2 = *(const ulonglong2*)&sB[(r0+2) * SBX + j2];
            ulonglong2 t3 = *(const ulonglong2*)&sB[(r0+3) * SBX + j2];
            ulonglong2 t4 = *(const ulonglong2*)&sB[(r0+4) * SBX + j2];
            ulonglong2 t5 = *(const ulonglong2*)&sB[(r0+5) * SBX + j2];
            ulonglong2 t6 = *(const ulonglong2*)&sB[(r0+6) * SBX + j2];
            ulonglong2 t7 = *(const ulonglong2*)&sB[(r0+7) * SBX + j2];
            *(ulonglong2*)&sA[(r0+0) * SBX + j2] =
                make_ulonglong2(tap5(t0.x,t1.x,t2.x,t3.x,t4.x,K0,K1,K2),
                                tap5(t0.y,t1.y,t2.y,t3.y,t4.y,K0,K1,K2));
            *(ulonglong2*)&sA[(r0+1) * SBX + j2] =
                make_ulonglong2(tap5(t1.x,t2.x,t3.x,t4.x,t5.x,K0,K1,K2),
                                tap5(t1.y,t2.y,t3.y,t4.y,t5.y,K0,K1,K2));
            *(ulonglong2*)&sA[(r0+2) * SBX + j2] =
                make_ulonglong2(tap5(t2.x,t3.x,t4.x,t5.x,t6.x,K0,K1,K2),
                                tap5(t2.y,t3.y,t4.y,t5.y,t6.y,K0,K1,K2));
            *(ulonglong2*)&sA[(r0+3) * SBX + j2] =
                make_ulonglong2(tap5(t3.x,t4.x,t5.x,t6.x,t7.x,K0,K1,K2),
                                tap5(t3.y,t4.y,t5.y,t6.y,t7.y,K0,K1,K2));
        }
    } else {
        #pragma unroll 1
        for (int e = tid; e < SBY * SBX; e += NT) {
            int i = e / SBX, j = e - i * SBX;
            int ii = clampi(y0 - 2 + i, H) - (y0 - 4);
            const u64* col = &sB[ii * SBX + j];
            sA[i * SBX + j] = tap5(col[-2*SBX], col[-SBX], col[0], col[SBX], col[2*SBX],
                                   K0, K1, K2);
        }
    }
    __syncthreads();

    // ---- Stage 4: Sobel/msq 2x2 -> sB[SMY][SMX] + packed NMS offsets ----
    #pragma unroll 1
    for (int s = tid; s < 17 * 33; s += NT) {
        int rp = s / 33, cp = s - rp * 33;
        int i0 = rp << 1, j0 = cp << 1;
        u64 v[4][4];
        #pragma unroll
        for (int r = 0; r < 4; r++) {
            const ulonglong2* pv = (const ulonglong2*)&sA[(i0 + r) * SBX + j0];
            ulonglong2 a = pv[0], b = pv[1];
            v[r][0] = a.x; v[r][1] = a.y; v[r][2] = b.x; v[r][3] = b.y;
        }
        u64 mres[2][2];
        #pragma unroll
        for (int di = 0; di < 2; di++) {
            #pragma unroll
            for (int dj = 0; dj < 2; dj++) {
                u64 a00 = v[di][dj],   a01 = v[di][dj+1],   a02 = v[di][dj+2];
                u64 a10 = v[di+1][dj],                      a12 = v[di+1][dj+2];
                u64 a20 = v[di+2][dj], a21 = v[di+2][dj+1], a22 = v[di+2][dj+2];
                u64 gx = ffma2(fsub2(a12, a10), TWO, fadd2(fsub2(a02, a00), fsub2(a22, a20)));
                u64 gy = ffma2(fsub2(a21, a01), TWO, fadd2(fsub2(a20, a00), fsub2(a22, a02)));
                int i = i0 + di, j = j0 + dj;
                int y = y0 - 1 + i, x = x0 - 1 + j;
                u64 msq = ffma2(gx, gx, fmul2(gy, gy));
                if (!((unsigned)y < H && (unsigned)x < W)) msq = 0ULL;
                mres[di][dj] = msq;
                if (i >= 1 && i <= TY && j >= 1 && j <= TX) {
                    float gxo, gxg, gyo, gyg;
                    upk(gx, gxo, gxg); upk(gy, gyo, gyg);
                    int oo = axis_off(gxo, gyo);
                    int og = axis_off(gxg, gyg);
                    snoff[(i - 1) * TX + (j - 1)] = (short)(oo | (og << 8));
                }
            }
        }
        *(ulonglong2*)&sB[(i0 + 0) * SMX + j0] = make_ulonglong2(mres[0][0], mres[0][1]);
        *(ulonglong2*)&sB[(i0 + 1) * SMX + j0] = make_ulonglong2(mres[1][0], mres[1][1]);
    }
    __syncthreads();

    // ---- Stage 5: NMS + threshold + XOR count ----
    int cnt = 0;
    const float* Bf = (const float*)sB;
    #pragma unroll
    for (int k = 0; k < 4; k++) {
        int px = tid + k * NT;
        int i = px >> 6, j = px & 63;
        int ci = (i + 1) * SMX + (j + 1);
        float co, cg;
        upk(sB[ci], co, cg);
        int sv = snoff[px];
        int oo = sv & 0xff;
        int og = (sv >> 8) & 0xff;
        bool eo = (co > Bf[2*(ci + oo)])     & (co > Bf[2*(ci - oo)])     & (co > TH2);
        bool eg = (cg > Bf[2*(ci + og) + 1]) & (cg > Bf[2*(ci - og) + 1]) & (cg > TH2);
        cnt += (int)(eo != eg);
    }

    // ---- block reduce + fused finalize ----
    #pragma unroll
    for (int o = 16; o > 0; o >>= 1)
        cnt += __shfl_down_sync(0xffffffffu, cnt, o);
    if ((tid & 31) == 0) wsum[tid >> 5] = cnt;
    __syncthreads();
    if (tid < (NT / 32)) {
        cnt = wsum[tid];
        #pragma unroll
        for (int o = (NT / 64); o > 0; o >>= 1)
            cnt += __shfl_down_sync(0xffffu, cnt, o);
        if (tid == 0) {
            atomicAdd(&g_count, cnt);
            __threadfence();
            int nb = gridDim.x * gridDim.y * gridDim.z;
            int t = atomicAdd(&g_ticket, 1);
            if (t == nb - 1) {
                out[0] = (float)atomicAdd(&g_count, 0) * inv_n;
                g_count = 0;
                g_ticket = 0;
            }
        }
    }
}

extern "C" void kernel_launch(void* const* d_in, const int* in_sizes, int n_in,
                              void* d_out, int out_size)
{
    const float* op = (const float*)d_in[0];
    const float* gt = (const float*)d_in[1];
    float* out = (float*)d_out;

    int batch = in_sizes[0] / (3 * HW);
    float inv_n = 1.0f / ((float)batch * HW);

    dim3 grid(W / TX, H / TY, batch);
    edge_loss_kernel<<<grid, NT>>>(op, gt, out, inv_n);
}

// round 5
// speedup vs baseline: 1.1993x; 1.1993x over previous
#include <cuda_runtime.h>
#include <math.h>

#define H 1024
#define W 1024
#define HW (H*W)
#define TX 64
#define TY 32
#define SGX 72
#define SGY 40
#define SBX 68
#define SBY 36
#define SMX 66
#define SMY 34
#define NT 512

typedef unsigned long long u64;

__device__ int g_count = 0;
__device__ int g_ticket = 0;

__device__ __forceinline__ u64 pk(float lo, float hi) {
    u64 r; asm("mov.b64 %0,{%1,%2};" : "=l"(r) : "f"(lo), "f"(hi)); return r;
}
__device__ __forceinline__ void upk(u64 v, float& lo, float& hi) {
    asm("mov.b64 {%0,%1},%2;" : "=f"(lo), "=f"(hi) : "l"(v));
}
__device__ __forceinline__ u64 fadd2(u64 a, u64 b) {
    u64 r; asm("add.rn.f32x2 %0,%1,%2;" : "=l"(r) : "l"(a), "l"(b)); return r;
}
__device__ __forceinline__ u64 fmul2(u64 a, u64 b) {
    u64 r; asm("mul.rn.f32x2 %0,%1,%2;" : "=l"(r) : "l"(a), "l"(b)); return r;
}
__device__ __forceinline__ u64 ffma2(u64 a, u64 b, u64 c) {
    u64 r; asm("fma.rn.f32x2 %0,%1,%2,%3;" : "=l"(r) : "l"(a), "l"(b), "l"(c)); return r;
}
__device__ __forceinline__ u64 fneg2(u64 a) { return a ^ 0x8000000080000000ULL; }
__device__ __forceinline__ u64 fsub2(u64 a, u64 b) { return fadd2(a, fneg2(b)); }

__device__ __forceinline__ int reflecti(int c, int n) {
    if (c < 0) c = -c;
    if (c >= n) c = 2*n - 2 - c;
    return c;
}
__device__ __forceinline__ int clampi(int c, int n) {
    return min(max(c, 0), n - 1);
}

#define GW0 0.05448868454964294f
#define GW1 0.24420134723186663f
#define GW2 0.4026199364369709f
#define T_LO 0.41421356237309503f
#define T_HI 2.414213562373095f
#define TH2  0.009999f

__device__ __forceinline__ int axis_off(float gx, float gy) {
    float ax = fabsf(gx), ay = fabsf(gy);
    if (ay <= T_LO * ax) return 1;
    if (ay >= T_HI * ax) return SMX;
    return ((__float_as_int(gx) ^ __float_as_int(gy)) >= 0) ? (SMX - 1) : (SMX + 1);
}

__device__ __forceinline__ u64 tap5(u64 t0, u64 t1, u64 t2, u64 t3, u64 t4,
                                    u64 K0, u64 K1, u64 K2) {
    u64 acc = fmul2(fadd2(t0, t4), K0);
    acc = ffma2(fadd2(t1, t3), K1, acc);
    return ffma2(t2, K2, acc);
}

__global__ __launch_bounds__(NT, 3)
void edge_loss_kernel(const float* __restrict__ op, const float* __restrict__ gt,
                      float* __restrict__ out, float inv_n)
{
    __shared__ u64   sA[SGY * SGX];
    __shared__ u64   sB[SGY * SBX];
    __shared__ short snoff[TY * TX];
    __shared__ int   wsum[NT / 32];

    const int tid = threadIdx.x;
    const int x0 = blockIdx.x * TX;
    const int y0 = blockIdx.y * TY;
    const size_t ib = (size_t)blockIdx.z * 3 * HW;
    const float* __restrict__ opi = op + ib;
    const float* __restrict__ gti = gt + ib;
    const bool xfast = (x0 != 0) && (x0 != W - TX);
    const bool yfast = (y0 != 0) && (y0 != H - TY);

    const u64 K0 = pk(GW0, GW0), K1 = pk(GW1, GW1), K2 = pk(GW2, GW2);
    const u64 TWO = pk(2.0f, 2.0f);

    // ---- Stage 1: grayscale pairs (reflect halo 4) -> sA[SGY][SGX] ----
    if (xfast) {
        #pragma unroll 1
        for (int g = tid; g < SGY * 18; g += NT) {
            int i = g / 18, q = g - i * 18;
            int yy = reflecti(y0 - 4 + i, H);
            const float* po = opi + yy * W + (x0 - 4) + q * 4;
            const float* pg = gti + yy * W + (x0 - 4) + q * 4;
            float4 ro = *(const float4*)(po);
            float4 go = *(const float4*)(po + HW);
            float4 bo = *(const float4*)(po + 2 * HW);
            float4 rg = *(const float4*)(pg);
            float4 gg = *(const float4*)(pg + HW);
            float4 bg = *(const float4*)(pg + 2 * HW);
            float o0 = fmaf(0.299f, ro.x, fmaf(0.587f, go.x, 0.114f * bo.x));
            float o1 = fmaf(0.299f, ro.y, fmaf(0.587f, go.y, 0.114f * bo.y));
            float o2 = fmaf(0.299f, ro.z, fmaf(0.587f, go.z, 0.114f * bo.z));
            float o3 = fmaf(0.299f, ro.w, fmaf(0.587f, go.w, 0.114f * bo.w));
            float t0 = fmaf(0.299f, rg.x, fmaf(0.587f, gg.x, 0.114f * bg.x));
            float t1 = fmaf(0.299f, rg.y, fmaf(0.587f, gg.y, 0.114f * bg.y));
            float t2 = fmaf(0.299f, rg.z, fmaf(0.587f, gg.z, 0.114f * bg.z));
            float t3 = fmaf(0.299f, rg.w, fmaf(0.587f, gg.w, 0.114f * bg.w));
            u64* dst = &sA[i * SGX + q * 4];
            *(ulonglong2*)(dst)     = make_ulonglong2(pk(o0, t0), pk(o1, t1));
            *(ulonglong2*)(dst + 2) = make_ulonglong2(pk(o2, t2), pk(o3, t3));
        }
    } else {
        #pragma unroll 1
        for (int e = tid; e < SGY * SGX; e += NT) {
            int i = e / SGX, j = e - i * SGX;
            int yy = reflecti(y0 - 4 + i, H);
            int xx = reflecti(x0 - 4 + j, W);
            int o = yy * W + xx;
            float a = fmaf(0.299f, opi[o], fmaf(0.587f, opi[o + HW], 0.114f * opi[o + 2*HW]));
            float b = fmaf(0.299f, gti[o], fmaf(0.587f, gti[o + HW], 0.114f * gti[o + 2*HW]));
            sA[e] = pk(a, b);
        }
    }
    __syncthreads();

    // ---- Stage 2: hblur 4-wide -> sB[SGY][SBX] ----
    if (xfast) {
        #pragma unroll 1
        for (int s = tid; s < SGY * 17; s += NT) {
            int i = s / 17;
            int j4 = (s - i * 17) << 2;
            const ulonglong2* rv = (const ulonglong2*)&sA[i * SGX + j4];
            ulonglong2 p0 = rv[0], p1 = rv[1], p2 = rv[2], p3 = rv[3];
            u64 o0 = tap5(p0.x, p0.y, p1.x, p1.y, p2.x, K0, K1, K2);
            u64 o1 = tap5(p0.y, p1.x, p1.y, p2.x, p2.y, K0, K1, K2);
            u64 o2 = tap5(p1.x, p1.y, p2.x, p2.y, p3.x, K0, K1, K2);
            u64 o3 = tap5(p1.y, p2.x, p2.y, p3.x, p3.y, K0, K1, K2);
            ulonglong2* w = (ulonglong2*)&sB[i * SBX + j4];
            w[0] = make_ulonglong2(o0, o1);
            w[1] = make_ulonglong2(o2, o3);
        }
    } else {
        #pragma unroll 1
        for (int e = tid; e < SGY * SBX; e += NT) {
            int i = e / SBX, j = e - i * SBX;
            int jj = clampi(x0 - 2 + j, W) - (x0 - 4);
            const u64* row = &sA[i * SGX + jj];
            sB[e] = tap5(row[-2], row[-1], row[0], row[1], row[2], K0, K1, K2);
        }
    }
    __syncthreads();

    // ---- Stage 3: vblur 2-tall x 2-wide -> sA[SBY][SBX] ----
    if (yfast) {
        #pragma unroll 1
        for (int s = tid; s < 18 * 34; s += NT) {
            int rg = s / 34;
            int j2 = (s - rg * 34) << 1;
            int r0 = rg << 1;
            ulonglong2 t0 = *(const ulonglong2*)&sB[(r0+0) * SBX + j2];
            ulonglong2 t1 = *(const ulonglong2*)&sB[(r0+1) * SBX + j2];
            ulonglong2 t2 = *(const ulonglong2*)&sB[(r0+2) * SBX + j2];
            ulonglong2 t3 = *(const ulonglong2*)&sB[(r0+3) * SBX + j2];
            ulonglong2 t4 = *(const ulonglong2*)&sB[(r0+4) * SBX + j2];
            ulonglong2 t5 = *(const ulonglong2*)&sB[(r0+5) * SBX + j2];
            *(ulonglong2*)&sA[(r0+0) * SBX + j2] =
                make_ulonglong2(tap5(t0.x,t1.x,t2.x,t3.x,t4.x,K0,K1,K2),
                                tap5(t0.y,t1.y,t2.y,t3.y,t4.y,K0,K1,K2));
            *(ulonglong2*)&sA[(r0+1) * SBX + j2] =
                make_ulonglong2(tap5(t1.x,t2.x,t3.x,t4.x,t5.x,K0,K1,K2),
                                tap5(t1.y,t2.y,t3.y,t4.y,t5.y,K0,K1,K2));
        }
    } else {
        #pragma unroll 1
        for (int e = tid; e < SBY * SBX; e += NT) {
            int i = e / SBX, j = e - i * SBX;
            int ii = clampi(y0 - 2 + i, H) - (y0 - 4);
            const u64* col = &sB[ii * SBX + j];
            sA[i * SBX + j] = tap5(col[-2*SBX], col[-SBX], col[0], col[SBX], col[2*SBX],
                                   K0, K1, K2);
        }
    }
    __syncthreads();

    // ---- Stage 4: Sobel/msq 1x2 -> sB[SMY][SMX] + packed NMS offsets ----
    #pragma unroll 1
    for (int s = tid; s < SMY * 33; s += NT) {
        int i = s / 33;
        int j0 = (s - i * 33) << 1;
        const ulonglong2* r0p = (const ulonglong2*)&sA[(i + 0) * SBX + j0];
        const ulonglong2* r1p = (const ulonglong2*)&sA[(i + 1) * SBX + j0];
        const ulonglong2* r2p = (const ulonglong2*)&sA[(i + 2) * SBX + j0];
        ulonglong2 r0a = r0p[0], r0b = r0p[1];
        ulonglong2 r1a = r1p[0], r1b = r1p[1];
        ulonglong2 r2a = r2p[0], r2b = r2p[1];

        int y = y0 - 1 + i;
        u64 mres[2];
        #pragma unroll
        for (int dj = 0; dj < 2; dj++) {
            u64 a00 = dj ? r0a.y : r0a.x;
            u64 a01 = dj ? r0b.x : r0a.y;
            u64 a02 = dj ? r0b.y : r0b.x;
            u64 a10 = dj ? r1a.y : r1a.x;
            u64 a12 = dj ? r1b.y : r1b.x;
            u64 a20 = dj ? r2a.y : r2a.x;
            u64 a21 = dj ? r2b.x : r2a.y;
            u64 a22 = dj ? r2b.y : r2b.x;
            u64 gx = ffma2(fsub2(a12, a10), TWO, fadd2(fsub2(a02, a00), fsub2(a22, a20)));
            u64 gy = ffma2(fsub2(a21, a01), TWO, fadd2(fsub2(a20, a00), fsub2(a22, a02)));
            int j = j0 + dj;
            int x = x0 - 1 + j;
            u64 msq = ffma2(gx, gx, fmul2(gy, gy));
            if (!((unsigned)y < H && (unsigned)x < W)) msq = 0ULL;
            mres[dj] = msq;
            if (i >= 1 && i <= TY && j >= 1 && j <= TX) {
                float gxo, gxg, gyo, gyg;
                upk(gx, gxo, gxg); upk(gy, gyo, gyg);
                int oo = axis_off(gxo, gyo);
                int og = axis_off(gxg, gyg);
                snoff[(i - 1) * TX + (j - 1)] = (short)(oo | (og << 8));
            }
        }
        *(ulonglong2*)&sB[i * SMX + j0] = make_ulonglong2(mres[0], mres[1]);
    }
    __syncthreads();

    // ---- Stage 5: NMS + threshold + XOR count ----
    int cnt = 0;
    const float* Bf = (const float*)sB;
    #pragma unroll
    for (int k = 0; k < 4; k++) {
        int px = tid + k * NT;
        int i = px >> 6, j = px & 63;
        int ci = (i + 1) * SMX + (j + 1);
        float co, cg;
        upk(sB[ci], co, cg);
        int sv = snoff[px];
        int oo = sv & 0xff;
        int og = (sv >> 8) & 0xff;
        bool eo = (co > Bf[2*(ci + oo)])     & (co > Bf[2*(ci - oo)])     & (co > TH2);
        bool eg = (cg > Bf[2*(ci + og) + 1]) & (cg > Bf[2*(ci - og) + 1]) & (cg > TH2);
        cnt += (int)(eo != eg);
    }

    // ---- block reduce + fused finalize ----
    #pragma unroll
    for (int o = 16; o > 0; o >>= 1)
        cnt += __shfl_down_sync(0xffffffffu, cnt, o);
    if ((tid & 31) == 0) wsum[tid >> 5] = cnt;
    __syncthreads();
    if (tid < (NT / 32)) {
        cnt = wsum[tid];
        #pragma unroll
        for (int o = (NT / 64); o > 0; o >>= 1)
            cnt += __shfl_down_sync(0xffffu, cnt, o);
        if (tid == 0) {
            atomicAdd(&g_count, cnt);
            __threadfence();
            int nb = gridDim.x * gridDim.y * gridDim.z;
            int t = atomicAdd(&g_ticket, 1);
            if (t == nb - 1) {
                out[0] = (float)atomicAdd(&g_count, 0) * inv_n;
                g_count = 0;
                g_ticket = 0;
            }
        }
    }
}

extern "C" void kernel_launch(void* const* d_in, const int* in_sizes, int n_in,
                              void* d_out, int out_size)
{
    const float* op = (const float*)d_in[0];
    const float* gt = (const float*)d_in[1];
    float* out = (float*)d_out;

    int batch = in_sizes[0] / (3 * HW);
    float inv_n = 1.0f / ((float)batch * HW);

    dim3 grid(W / TX, H / TY, batch);
    edge_loss_kernel<<<grid, NT>>>(op, gt, out, inv_n);
}

// round 6
// speedup vs baseline: 1.2694x; 1.0584x over previous
#include <cuda_runtime.h>
#include <math.h>

#define H 1024
#define W 1024
#define HW (H*W)
#define TX 64
#define TY 32
#define SGX 72
#define SGY 40
#define SBX 68
#define SBY 36
#define SMX 66
#define SMY 34
#define NT 512

typedef unsigned long long u64;

__device__ int g_count = 0;
__device__ int g_ticket = 0;

__device__ __forceinline__ u64 pk(float lo, float hi) {
    u64 r; asm("mov.b64 %0,{%1,%2};" : "=l"(r) : "f"(lo), "f"(hi)); return r;
}
__device__ __forceinline__ void upk(u64 v, float& lo, float& hi) {
    asm("mov.b64 {%0,%1},%2;" : "=f"(lo), "=f"(hi) : "l"(v));
}
__device__ __forceinline__ u64 fadd2(u64 a, u64 b) {
    u64 r; asm("add.rn.f32x2 %0,%1,%2;" : "=l"(r) : "l"(a), "l"(b)); return r;
}
__device__ __forceinline__ u64 fmul2(u64 a, u64 b) {
    u64 r; asm("mul.rn.f32x2 %0,%1,%2;" : "=l"(r) : "l"(a), "l"(b)); return r;
}
__device__ __forceinline__ u64 ffma2(u64 a, u64 b, u64 c) {
    u64 r; asm("fma.rn.f32x2 %0,%1,%2,%3;" : "=l"(r) : "l"(a), "l"(b), "l"(c)); return r;
}
__device__ __forceinline__ u64 fneg2(u64 a) { return a ^ 0x8000000080000000ULL; }
__device__ __forceinline__ u64 fsub2(u64 a, u64 b) { return fadd2(a, fneg2(b)); }

__device__ __forceinline__ int reflecti(int c, int n) {
    if (c < 0) c = -c;
    if (c >= n) c = 2*n - 2 - c;
    return c;
}
__device__ __forceinline__ int clampi(int c, int n) {
    return min(max(c, 0), n - 1);
}

#define GW0 0.05448868454964294f
#define GW1 0.24420134723186663f
#define GW2 0.4026199364369709f
#define T_LO 0.41421356237309503f
#define T_HI 2.414213562373095f
#define TH2  0.009999f

__device__ __forceinline__ int axis_off(float gx, float gy) {
    float ax = fabsf(gx), ay = fabsf(gy);
    if (ay <= T_LO * ax) return 1;
    if (ay >= T_HI * ax) return SMX;
    return ((__float_as_int(gx) ^ __float_as_int(gy)) >= 0) ? (SMX - 1) : (SMX + 1);
}

__device__ __forceinline__ u64 tap5(u64 t0, u64 t1, u64 t2, u64 t3, u64 t4,
                                    u64 K0, u64 K1, u64 K2) {
    u64 acc = fmul2(fadd2(t0, t4), K0);
    acc = ffma2(fadd2(t1, t3), K1, acc);
    return ffma2(t2, K2, acc);
}

__global__ __launch_bounds__(NT, 3)
void edge_loss_kernel(const float* __restrict__ op, const float* __restrict__ gt,
                      float* __restrict__ out, float inv_n)
{
    __shared__ u64   sA[SGY * SGX];
    __shared__ u64   sB[SGY * SBX];
    __shared__ short snoff[TY * TX];
    __shared__ int   wsum[NT / 32];

    const int tid = threadIdx.x;
    const int x0 = blockIdx.x * TX;
    const int y0 = blockIdx.y * TY;
    const size_t ib = (size_t)blockIdx.z * 3 * HW;
    const float* __restrict__ opi = op + ib;
    const float* __restrict__ gti = gt + ib;
    const bool xfast = (x0 != 0) && (x0 != W - TX);
    const bool yfast = (y0 != 0) && (y0 != H - TY);

    const u64 K0 = pk(GW0, GW0), K1 = pk(GW1, GW1), K2 = pk(GW2, GW2);
    const u64 TWO = pk(2.0f, 2.0f);

    // ---- Stage 1: grayscale pairs (reflect halo 4) -> sA[SGY][SGX]
    //      2 px/thread, 16B lane stride: conflict-free STS.128 ----
    if (xfast) {
        #pragma unroll 1
        for (int g = tid; g < SGY * 36; g += NT) {
            int i = g / 36, q = g - i * 36;      // q: ulonglong2 index in row
            int yy = reflecti(y0 - 4 + i, H);
            const float* po = opi + yy * W + (x0 - 4) + q * 2;
            const float* pg = gti + yy * W + (x0 - 4) + q * 2;
            float2 ro = *(const float2*)(po);
            float2 go = *(const float2*)(po + HW);
            float2 bo = *(const float2*)(po + 2 * HW);
            float2 rg = *(const float2*)(pg);
            float2 gg = *(const float2*)(pg + HW);
            float2 bg = *(const float2*)(pg + 2 * HW);
            float o0 = fmaf(0.299f, ro.x, fmaf(0.587f, go.x, 0.114f * bo.x));
            float o1 = fmaf(0.299f, ro.y, fmaf(0.587f, go.y, 0.114f * bo.y));
            float t0 = fmaf(0.299f, rg.x, fmaf(0.587f, gg.x, 0.114f * bg.x));
            float t1 = fmaf(0.299f, rg.y, fmaf(0.587f, gg.y, 0.114f * bg.y));
            *(ulonglong2*)&sA[i * SGX + q * 2] = make_ulonglong2(pk(o0, t0), pk(o1, t1));
        }
    } else {
        #pragma unroll 1
        for (int e = tid; e < SGY * SGX; e += NT) {
            int i = e / SGX, j = e - i * SGX;
            int yy = reflecti(y0 - 4 + i, H);
            int xx = reflecti(x0 - 4 + j, W);
            int o = yy * W + xx;
            float a = fmaf(0.299f, opi[o], fmaf(0.587f, opi[o + HW], 0.114f * opi[o + 2*HW]));
            float b = fmaf(0.299f, gti[o], fmaf(0.587f, gti[o + HW], 0.114f * gti[o + 2*HW]));
            sA[e] = pk(a, b);
        }
    }
    __syncthreads();

    // ---- Stage 2: hblur 2-wide -> sB[SGY][SBX]; 16B lane stride, conflict-free ----
    if (xfast) {
        #pragma unroll 1
        for (int s = tid; s < SGY * 34; s += NT) {
            int i = s / 34;
            int j2 = (s - i * 34) << 1;
            const ulonglong2* rv = (const ulonglong2*)&sA[i * SGX + j2];
            ulonglong2 p0 = rv[0], p1 = rv[1], p2 = rv[2];
            u64 o0 = tap5(p0.x, p0.y, p1.x, p1.y, p2.x, K0, K1, K2);
            u64 o1 = tap5(p0.y, p1.x, p1.y, p2.x, p2.y, K0, K1, K2);
            *(ulonglong2*)&sB[i * SBX + j2] = make_ulonglong2(o0, o1);
        }
    } else {
        #pragma unroll 1
        for (int e = tid; e < SGY * SBX; e += NT) {
            int i = e / SBX, j = e - i * SBX;
            int jj = clampi(x0 - 2 + j, W) - (x0 - 4);
            const u64* row = &sA[i * SGX + jj];
            sB[e] = tap5(row[-2], row[-1], row[0], row[1], row[2], K0, K1, K2);
        }
    }
    __syncthreads();

    // ---- Stage 3: vblur 2-tall x 2-wide -> sA[SBY][SBX] ----
    if (yfast) {
        #pragma unroll 1
        for (int s = tid; s < 18 * 34; s += NT) {
            int rg = s / 34;
            int j2 = (s - rg * 34) << 1;
            int r0 = rg << 1;
            ulonglong2 t0 = *(const ulonglong2*)&sB[(r0+0) * SBX + j2];
            ulonglong2 t1 = *(const ulonglong2*)&sB[(r0+1) * SBX + j2];
            ulonglong2 t2 = *(const ulonglong2*)&sB[(r0+2) * SBX + j2];
            ulonglong2 t3 = *(const ulonglong2*)&sB[(r0+3) * SBX + j2];
            ulonglong2 t4 = *(const ulonglong2*)&sB[(r0+4) * SBX + j2];
            ulonglong2 t5 = *(const ulonglong2*)&sB[(r0+5) * SBX + j2];
            *(ulonglong2*)&sA[(r0+0) * SBX + j2] =
                make_ulonglong2(tap5(t0.x,t1.x,t2.x,t3.x,t4.x,K0,K1,K2),
                                tap5(t0.y,t1.y,t2.y,t3.y,t4.y,K0,K1,K2));
            *(ulonglong2*)&sA[(r0+1) * SBX + j2] =
                make_ulonglong2(tap5(t1.x,t2.x,t3.x,t4.x,t5.x,K0,K1,K2),
                                tap5(t1.y,t2.y,t3.y,t4.y,t5.y,K0,K1,K2));
        }
    } else {
        #pragma unroll 1
        for (int e = tid; e < SBY * SBX; e += NT) {
            int i = e / SBX, j = e - i * SBX;
            int ii = clampi(y0 - 2 + i, H) - (y0 - 4);
            const u64* col = &sB[ii * SBX + j];
            sA[i * SBX + j] = tap5(col[-2*SBX], col[-SBX], col[0], col[SBX], col[2*SBX],
                                   K0, K1, K2);
        }
    }
    __syncthreads();

    // ---- Stage 4: Sobel/msq 1x2 -> sB[SMY][SMX] + packed NMS offsets ----
    #pragma unroll 1
    for (int s = tid; s < SMY * 33; s += NT) {
        int i = s / 33;
        int j0 = (s - i * 33) << 1;
        const ulonglong2* r0p = (const ulonglong2*)&sA[(i + 0) * SBX + j0];
        const ulonglong2* r1p = (const ulonglong2*)&sA[(i + 1) * SBX + j0];
        const ulonglong2* r2p = (const ulonglong2*)&sA[(i + 2) * SBX + j0];
        ulonglong2 r0a = r0p[0], r0b = r0p[1];
        ulonglong2 r1a = r1p[0], r1b = r1p[1];
        ulonglong2 r2a = r2p[0], r2b = r2p[1];

        int y = y0 - 1 + i;
        u64 mres[2];
        #pragma unroll
        for (int dj = 0; dj < 2; dj++) {
            u64 a00 = dj ? r0a.y : r0a.x;
            u64 a01 = dj ? r0b.x : r0a.y;
            u64 a02 = dj ? r0b.y : r0b.x;
            u64 a10 = dj ? r1a.y : r1a.x;
            u64 a12 = dj ? r1b.y : r1b.x;
            u64 a20 = dj ? r2a.y : r2a.x;
            u64 a21 = dj ? r2b.x : r2a.y;
            u64 a22 = dj ? r2b.y : r2b.x;
            u64 gx = ffma2(fsub2(a12, a10), TWO, fadd2(fsub2(a02, a00), fsub2(a22, a20)));
            u64 gy = ffma2(fsub2(a21, a01), TWO, fadd2(fsub2(a20, a00), fsub2(a22, a02)));
            int j = j0 + dj;
            int x = x0 - 1 + j;
            u64 msq = ffma2(gx, gx, fmul2(gy, gy));
            if (!((unsigned)y < H && (unsigned)x < W)) msq = 0ULL;
            mres[dj] = msq;
            if (i >= 1 && i <= TY && j >= 1 && j <= TX) {
                float gxo, gxg, gyo, gyg;
                upk(gx, gxo, gxg); upk(gy, gyo, gyg);
                int oo = axis_off(gxo, gyo);
                int og = axis_off(gxg, gyg);
                snoff[(i - 1) * TX + (j - 1)] = (short)(oo | (og << 8));
            }
        }
        *(ulonglong2*)&sB[i * SMX + j0] = make_ulonglong2(mres[0], mres[1]);
    }
    __syncthreads();

    // ---- Stage 5: NMS + threshold + XOR count ----
    int cnt = 0;
    const float* Bf = (const float*)sB;
    #pragma unroll
    for (int k = 0; k < 4; k++) {
        int px = tid + k * NT;
        int i = px >> 6, j = px & 63;
        int ci = (i + 1) * SMX + (j + 1);
        float co, cg;
        upk(sB[ci], co, cg);
        int sv = snoff[px];
        int oo = sv & 0xff;
        int og = (sv >> 8) & 0xff;
        bool eo = (co > Bf[2*(ci + oo)])     & (co > Bf[2*(ci - oo)])     & (co > TH2);
        bool eg = (cg > Bf[2*(ci + og) + 1]) & (cg > Bf[2*(ci - og) + 1]) & (cg > TH2);
        cnt += (int)(eo != eg);
    }

    // ---- block reduce + fused finalize ----
    #pragma unroll
    for (int o = 16; o > 0; o >>= 1)
        cnt += __shfl_down_sync(0xffffffffu, cnt, o);
    if ((tid & 31) == 0) wsum[tid >> 5] = cnt;
    __syncthreads();
    if (tid < (NT / 32)) {
        cnt = wsum[tid];
        #pragma unroll
        for (int o = (NT / 64); o > 0; o >>= 1)
            cnt += __shfl_down_sync(0xffffu, cnt, o);
        if (tid == 0) {
            atomicAdd(&g_count, cnt);
            __threadfence();
            int nb = gridDim.x * gridDim.y * gridDim.z;
            int t = atomicAdd(&g_ticket, 1);
            if (t == nb - 1) {
                out[0] = (float)atomicAdd(&g_count, 0) * inv_n;
                g_count = 0;
                g_ticket = 0;
            }
        }
    }
}

extern "C" void kernel_launch(void* const* d_in, const int* in_sizes, int n_in,
                              void* d_out, int out_size)
{
    const float* op = (const float*)d_in[0];
    const float* gt = (const float*)d_in[1];
    float* out = (float*)d_out;

    int batch = in_sizes[0] / (3 * HW);
    float inv_n = 1.0f / ((float)batch * HW);

    dim3 grid(W / TX, H / TY, batch);
    edge_loss_kernel<<<grid, NT>>>(op, gt, out, inv_n);
}

// round 7
// speedup vs baseline: 1.2876x; 1.0143x over previous
#include <cuda_runtime.h>
#include <math.h>

#define H 1024
#define W 1024
#define HW (H*W)
#define TX 64
#define TY 32
#define SGX 72
#define SGY 40
#define SBX 68
#define SBY 36
#define SMX 66
#define SMY 34
#define NT 512

typedef unsigned long long u64;

__device__ int g_count = 0;
__device__ int g_ticket = 0;

__device__ __forceinline__ u64 pk(float lo, float hi) {
    u64 r; asm("mov.b64 %0,{%1,%2};" : "=l"(r) : "f"(lo), "f"(hi)); return r;
}
__device__ __forceinline__ void upk(u64 v, float& lo, float& hi) {
    asm("mov.b64 {%0,%1},%2;" : "=f"(lo), "=f"(hi) : "l"(v));
}
__device__ __forceinline__ u64 fadd2(u64 a, u64 b) {
    u64 r; asm("add.rn.f32x2 %0,%1,%2;" : "=l"(r) : "l"(a), "l"(b)); return r;
}
__device__ __forceinline__ u64 fmul2(u64 a, u64 b) {
    u64 r; asm("mul.rn.f32x2 %0,%1,%2;" : "=l"(r) : "l"(a), "l"(b)); return r;
}
__device__ __forceinline__ u64 ffma2(u64 a, u64 b, u64 c) {
    u64 r; asm("fma.rn.f32x2 %0,%1,%2,%3;" : "=l"(r) : "l"(a), "l"(b), "l"(c)); return r;
}
__device__ __forceinline__ u64 fneg2(u64 a) { return a ^ 0x8000000080000000ULL; }
__device__ __forceinline__ u64 fsub2(u64 a, u64 b) { return fadd2(a, fneg2(b)); }

__device__ __forceinline__ int reflecti(int c, int n) {
    if (c < 0) c = -c;
    if (c >= n) c = 2*n - 2 - c;
    return c;
}

#define GW0 0.05448868454964294f
#define GW1 0.24420134723186663f
#define GW2 0.4026199364369709f
#define T_LO 0.41421356237309503f
#define T_HI 2.414213562373095f
#define TH2  0.009999f

__device__ __forceinline__ int axis_off(float gx, float gy) {
    float ax = fabsf(gx), ay = fabsf(gy);
    if (ay <= T_LO * ax) return 1;
    if (ay >= T_HI * ax) return SMX;
    return ((__float_as_int(gx) ^ __float_as_int(gy)) >= 0) ? (SMX - 1) : (SMX + 1);
}

__device__ __forceinline__ u64 tap5(u64 t0, u64 t1, u64 t2, u64 t3, u64 t4,
                                    u64 K0, u64 K1, u64 K2) {
    u64 acc = fmul2(fadd2(t0, t4), K0);
    acc = ffma2(fadd2(t1, t3), K1, acc);
    return ffma2(t2, K2, acc);
}

__global__ __launch_bounds__(NT, 3)
void edge_loss_kernel(const float* __restrict__ op, const float* __restrict__ gt,
                      float* __restrict__ out, float inv_n)
{
    __shared__ u64   sA[SGY * SGX];
    __shared__ u64   sB[SGY * SBX];
    __shared__ short snoff[TY * TX];
    __shared__ int   wsum[NT / 32];

    const int tid = threadIdx.x;
    const int x0 = blockIdx.x * TX;
    const int y0 = blockIdx.y * TY;
    const size_t ib = (size_t)blockIdx.z * 3 * HW;
    const float* __restrict__ opi = op + ib;
    const float* __restrict__ gti = gt + ib;

    const u64 K0 = pk(GW0, GW0), K1 = pk(GW1, GW1), K2 = pk(GW2, GW2);
    const u64 TWO = pk(2.0f, 2.0f);

    // ---- Stage 1: grayscale pairs (reflect halo 4) -> sA[SGY][SGX]
    //      Uniform fast path; OOR pairs skipped and reflect-patched after.
    #pragma unroll 1
    for (int g = tid; g < SGY * 36; g += NT) {
        int i = g / 36, q = g - i * 36;
        int xlo = x0 - 4 + q * 2;
        if ((unsigned)xlo <= (unsigned)(W - 2)) {
            int yy = reflecti(y0 - 4 + i, H);
            const float* po = opi + yy * W + xlo;
            const float* pg = gti + yy * W + xlo;
            float2 ro = *(const float2*)(po);
            float2 go = *(const float2*)(po + HW);
            float2 bo = *(const float2*)(po + 2 * HW);
            float2 rg = *(const float2*)(pg);
            float2 gg = *(const float2*)(pg + HW);
            float2 bg = *(const float2*)(pg + 2 * HW);
            float o0 = fmaf(0.299f, ro.x, fmaf(0.587f, go.x, 0.114f * bo.x));
            float o1 = fmaf(0.299f, ro.y, fmaf(0.587f, go.y, 0.114f * bo.y));
            float t0 = fmaf(0.299f, rg.x, fmaf(0.587f, gg.x, 0.114f * bg.x));
            float t1 = fmaf(0.299f, rg.y, fmaf(0.587f, gg.y, 0.114f * bg.y));
            *(ulonglong2*)&sA[i * SGX + q * 2] = make_ulonglong2(pk(o0, t0), pk(o1, t1));
        }
    }
    __syncthreads();

    // ---- Stage 1 patch: x-border reflect copies (block-uniform branch) ----
    if (x0 == 0) {
        #pragma unroll 1
        for (int e = tid; e < SGY * 4; e += NT) {
            int r = e >> 2, j = e & 3;
            sA[r * SGX + j] = sA[r * SGX + (8 - j)];
        }
        __syncthreads();
    } else if (x0 == W - TX) {
        #pragma unroll 1
        for (int e = tid; e < SGY * 4; e += NT) {
            int r = e >> 2, j = 68 + (e & 3);
            sA[r * SGX + j] = sA[r * SGX + (134 - j)];
        }
        __syncthreads();
    }

    // ---- Stage 2: hblur 2-wide -> sB[SGY][SBX] (uniform fast path) ----
    #pragma unroll 1
    for (int s = tid; s < SGY * 34; s += NT) {
        int i = s / 34;
        int j2 = (s - i * 34) << 1;
        const ulonglong2* rv = (const ulonglong2*)&sA[i * SGX + j2];
        ulonglong2 p0 = rv[0], p1 = rv[1], p2 = rv[2];
        u64 o0 = tap5(p0.x, p0.y, p1.x, p1.y, p2.x, K0, K1, K2);
        u64 o1 = tap5(p0.y, p1.x, p1.y, p2.x, p2.y, K0, K1, K2);
        *(ulonglong2*)&sB[i * SBX + j2] = make_ulonglong2(o0, o1);
    }
    __syncthreads();

    // ---- Stage 2 patch: x edge-clamp of blurred field ----
    if (x0 == 0) {
        #pragma unroll 1
        for (int r = tid; r < SGY; r += NT) {
            u64 v = sB[r * SBX + 2];
            sB[r * SBX + 0] = v;
            sB[r * SBX + 1] = v;
        }
        __syncthreads();
    } else if (x0 == W - TX) {
        #pragma unroll 1
        for (int r = tid; r < SGY; r += NT) {
            u64 v = sB[r * SBX + 65];
            sB[r * SBX + 66] = v;
            sB[r * SBX + 67] = v;
        }
        __syncthreads();
    }

    // ---- Stage 3: vblur 2-tall x 2-wide -> sA[SBY][SBX] (uniform fast path) ----
    #pragma unroll 1
    for (int s = tid; s < 18 * 34; s += NT) {
        int rg = s / 34;
        int j2 = (s - rg * 34) << 1;
        int r0 = rg << 1;
        ulonglong2 t0 = *(const ulonglong2*)&sB[(r0+0) * SBX + j2];
        ulonglong2 t1 = *(const ulonglong2*)&sB[(r0+1) * SBX + j2];
        ulonglong2 t2 = *(const ulonglong2*)&sB[(r0+2) * SBX + j2];
        ulonglong2 t3 = *(const ulonglong2*)&sB[(r0+3) * SBX + j2];
        ulonglong2 t4 = *(const ulonglong2*)&sB[(r0+4) * SBX + j2];
        ulonglong2 t5 = *(const ulonglong2*)&sB[(r0+5) * SBX + j2];
        *(ulonglong2*)&sA[(r0+0) * SBX + j2] =
            make_ulonglong2(tap5(t0.x,t1.x,t2.x,t3.x,t4.x,K0,K1,K2),
                            tap5(t0.y,t1.y,t2.y,t3.y,t4.y,K0,K1,K2));
        *(ulonglong2*)&sA[(r0+1) * SBX + j2] =
            make_ulonglong2(tap5(t1.x,t2.x,t3.x,t4.x,t5.x,K0,K1,K2),
                            tap5(t1.y,t2.y,t3.y,t4.y,t5.y,K0,K1,K2));
    }
    __syncthreads();

    // ---- Stage 3 patch: y edge-clamp of blurred field ----
    if (y0 == 0) {
        #pragma unroll 1
        for (int j = tid; j < SBX; j += NT) {
            u64 v = sA[2 * SBX + j];
            sA[0 * SBX + j] = v;
            sA[1 * SBX + j] = v;
        }
        __syncthreads();
    } else if (y0 == H - TY) {
        #pragma unroll 1
        for (int j = tid; j < SBX; j += NT) {
            u64 v = sA[33 * SBX + j];
            sA[34 * SBX + j] = v;
            sA[35 * SBX + j] = v;
        }
        __syncthreads();
    }

    // ---- Stage 4: Sobel/msq 1x2 -> sB[SMY][SMX] + packed NMS offsets ----
    #pragma unroll 1
    for (int s = tid; s < SMY * 33; s += NT) {
        int i = s / 33;
        int j0 = (s - i * 33) << 1;
        const ulonglong2* r0p = (const ulonglong2*)&sA[(i + 0) * SBX + j0];
        const ulonglong2* r1p = (const ulonglong2*)&sA[(i + 1) * SBX + j0];
        const ulonglong2* r2p = (const ulonglong2*)&sA[(i + 2) * SBX + j0];
        ulonglong2 r0a = r0p[0], r0b = r0p[1];
        ulonglong2 r1a = r1p[0], r1b = r1p[1];
        ulonglong2 r2a = r2p[0], r2b = r2p[1];

        int y = y0 - 1 + i;
        u64 mres[2];
        #pragma unroll
        for (int dj = 0; dj < 2; dj++) {
            u64 a00 = dj ? r0a.y : r0a.x;
            u64 a01 = dj ? r0b.x : r0a.y;
            u64 a02 = dj ? r0b.y : r0b.x;
            u64 a10 = dj ? r1a.y : r1a.x;
            u64 a12 = dj ? r1b.y : r1b.x;
            u64 a20 = dj ? r2a.y : r2a.x;
            u64 a21 = dj ? r2b.x : r2a.y;
            u64 a22 = dj ? r2b.y : r2b.x;
            u64 gx = ffma2(fsub2(a12, a10), TWO, fadd2(fsub2(a02, a00), fsub2(a22, a20)));
            u64 gy = ffma2(fsub2(a21, a01), TWO, fadd2(fsub2(a20, a00), fsub2(a22, a02)));
            int j = j0 + dj;
            int x = x0 - 1 + j;
            u64 msq = ffma2(gx, gx, fmul2(gy, gy));
            if (!((unsigned)y < H && (unsigned)x < W)) msq = 0ULL;
            mres[dj] = msq;
            if (i >= 1 && i <= TY && j >= 1 && j <= TX) {
                float gxo, gxg, gyo, gyg;
                upk(gx, gxo, gxg); upk(gy, gyo, gyg);
                int oo = axis_off(gxo, gyo);
                int og = axis_off(gxg, gyg);
                snoff[(i - 1) * TX + (j - 1)] = (short)(oo | (og << 8));
            }
        }
        *(ulonglong2*)&sB[i * SMX + j0] = make_ulonglong2(mres[0], mres[1]);
    }
    __syncthreads();

    // ---- Stage 5: NMS + threshold + XOR count ----
    int cnt = 0;
    const float* Bf = (const float*)sB;
    #pragma unroll
    for (int k = 0; k < 4; k++) {
        int px = tid + k * NT;
        int i = px >> 6, j = px & 63;
        int ci = (i + 1) * SMX + (j + 1);
        float co, cg;
        upk(sB[ci], co, cg);
        int sv = snoff[px];
        int oo = sv & 0xff;
        int og = (sv >> 8) & 0xff;
        bool eo = (co > Bf[2*(ci + oo)])     & (co > Bf[2*(ci - oo)])     & (co > TH2);
        bool eg = (cg > Bf[2*(ci + og) + 1]) & (cg > Bf[2*(ci - og) + 1]) & (cg > TH2);
        cnt += (int)(eo != eg);
    }

    // ---- block reduce + fused finalize ----
    #pragma unroll
    for (int o = 16; o > 0; o >>= 1)
        cnt += __shfl_down_sync(0xffffffffu, cnt, o);
    if ((tid & 31) == 0) wsum[tid >> 5] = cnt;
    __syncthreads();
    if (tid < (NT / 32)) {
        cnt = wsum[tid];
        #pragma unroll
        for (int o = (NT / 64); o > 0; o >>= 1)
            cnt += __shfl_down_sync(0xffffu, cnt, o);
        if (tid == 0) {
            atomicAdd(&g_count, cnt);
            __threadfence();
            int nb = gridDim.x * gridDim.y * gridDim.z;
            int t = atomicAdd(&g_ticket, 1);
            if (t == nb - 1) {
                out[0] = (float)atomicAdd(&g_count, 0) * inv_n;
                g_count = 0;
                g_ticket = 0;
            }
        }
    }
}

extern "C" void kernel_launch(void* const* d_in, const int* in_sizes, int n_in,
                              void* d_out, int out_size)
{
    const float* op = (const float*)d_in[0];
    const float* gt = (const float*)d_in[1];
    float* out = (float*)d_out;

    int batch = in_sizes[0] / (3 * HW);
    float inv_n = 1.0f / ((float)batch * HW);

    dim3 grid(W / TX, H / TY, batch);
    edge_loss_kernel<<<grid, NT>>>(op, gt, out, inv_n);
}